// round 14
// baseline (speedup 1.0000x reference)
#include <cuda_runtime.h>
#include <cstdint>

#define H_IN 160
#define W_IN 288
#define HO   80
#define WO   144
#define NPIX (HO*WO)          // 11520
#define BATCH 4
#define EPSV 1e-5f
#define DISP 24

// ------------------- scratch (static device memory, no allocs) ---------------
__device__ float g_y1g[BATCH*192*NPIX];
__device__ float g_y1c[BATCH*24*NPIX];
__device__ float g_g8 [BATCH*96*NPIX];
__device__ float g_c8 [BATCH*12*NPIX];
__device__ unsigned g_wc1hi[27*192*16];
__device__ unsigned g_wc1lo[27*192*16];
__device__ unsigned g_w2hi [6*144*16];
__device__ unsigned g_w2lo [6*144*16];

// ===================== small helpers ========================================
__device__ __forceinline__ unsigned smem_u32(const void* p){
    unsigned a;
    asm("{ .reg .u64 t; cvta.to.shared.u64 t, %1; cvt.u32.u64 %0, t; }"
        : "=r"(a) : "l"(p));
    return a;
}
__device__ __forceinline__ unsigned short bf16hi(float x){
    unsigned u = __float_as_uint(x);
    unsigned r = u + 0x7fffu + ((u >> 16) & 1u);
    return (unsigned short)(r >> 16);
}
__device__ __forceinline__ float bf16f(unsigned short h){
    return __uint_as_float(((unsigned)h) << 16);
}
__device__ __forceinline__ unsigned pack2(unsigned short a, unsigned short b){
    return (unsigned)a | ((unsigned)b << 16);
}
__device__ __forceinline__ void ldm4(unsigned* r, unsigned addr){
    asm volatile("ldmatrix.sync.aligned.m8n8.x4.shared.b16 {%0,%1,%2,%3}, [%4];"
        : "=r"(r[0]), "=r"(r[1]), "=r"(r[2]), "=r"(r[3]) : "r"(addr));
}
__device__ __forceinline__ void mma_bf16(float* c, const unsigned* a,
                                         unsigned b0, unsigned b1){
    asm volatile("mma.sync.aligned.m16n8k16.row.col.f32.bf16.bf16.f32 "
        "{%0,%1,%2,%3}, {%4,%5,%6,%7}, {%8,%9}, {%0,%1,%2,%3};"
        : "+f"(c[0]), "+f"(c[1]), "+f"(c[2]), "+f"(c[3])
        : "r"(a[0]), "r"(a[1]), "r"(a[2]), "r"(a[3]), "r"(b0), "r"(b1));
}

// ===================== weight prep ==========================================
__global__ __launch_bounds__(256) void wprep(const float* __restrict__ w1,
                                             const float* __restrict__ w2,
                                             unsigned* __restrict__ w1hi,
                                             unsigned* __restrict__ w1lo,
                                             unsigned* __restrict__ w2hi,
                                             unsigned* __restrict__ w2lo)
{
    int idx = blockIdx.x * 256 + threadIdx.x;
    if (idx < 27*192*16) {
        int kk = idx & 15;
        int row = (idx >> 4) % 192;
        int c   = idx / (192*16);
        int k0 = c*32 + 2*kk, k1 = k0 + 1;
        int tap0 = k0 / 96, ic0 = k0 - tap0*96;
        int tap1 = k1 / 96, ic1 = k1 - tap1*96;
        float v0 = w1[row*864 + ic0*9 + tap0];
        float v1 = w1[row*864 + ic1*9 + tap1];
        unsigned short h0 = bf16hi(v0), h1 = bf16hi(v1);
        w1hi[idx] = pack2(h0, h1);
        w1lo[idx] = pack2(bf16hi(v0 - bf16f(h0)), bf16hi(v1 - bf16f(h1)));
    } else {
        int j = idx - 27*192*16;
        if (j >= 6*144*16) return;
        int kk = j & 15;
        int row = (j >> 4) % 144;
        int c   = j / (144*16);
        int k0 = c*32 + 2*kk;
        float v0 = w2[row*192 + k0];
        float v1 = w2[row*192 + k0 + 1];
        unsigned short h0 = bf16hi(v0), h1 = bf16hi(v1);
        w2hi[j] = pack2(h0, h1);
        w2lo[j] = pack2(bf16hi(v0 - bf16f(h0)), bf16hi(v1 - bf16f(h1)));
    }
}

// ===================== stage1: conv1 gwc(MMA,512thr, double-buffered) + cat ==
#define S1_STG0 1536
#define S1_STGSZ 51200
#define SMEM_S1 (1536 + 2*S1_STGSZ)   // 103936

__global__ __launch_bounds__(512, 1) void stage1(
    const float* __restrict__ x,
    const unsigned* __restrict__ whi, const unsigned* __restrict__ wlo,
    const float* __restrict__ bng, const float* __restrict__ bnb,
    const float* __restrict__ bnm, const float* __restrict__ bnv,
    float* __restrict__ y,
    const float* __restrict__ xc_in, const float* __restrict__ wc,
    const float* __restrict__ cbg, const float* __restrict__ cbb,
    const float* __restrict__ cbm, const float* __restrict__ cbv,
    float* __restrict__ yc)
{
    extern __shared__ char smem[];
    const int tid = threadIdx.x;

    if (blockIdx.x < 360) {
        const unsigned sb = smem_u32(smem);
        const int wid = tid >> 5, lane = tid & 31;
        float* sbn = (float*)smem;

        if (tid < 192) {
            float s = bng[tid] * rsqrtf(bnv[tid] + EPSV);
            sbn[tid] = s;
            sbn[192 + tid] = bnb[tid] - bnm[tid] * s;
        }

        const int m  = tid & 127;
        const int kq = tid >> 7;
        const int p  = blockIdx.x*128 + m;
        const int b  = p / NPIX;
        const int r  = p - b*NPIX;
        const int ho = r / WO, wo = r - (r/WO)*WO;
        const float* xb = x + (size_t)b * 96 * H_IN * W_IN;

        const int brow = tid >> 2, bq4 = (tid & 3)*4;

        const int wm = wid & 3, wn = wid >> 2;
        const unsigned aOff = ((wm*32 + (lane&15))*40 + (lane>>4)*8)*2;
        const unsigned bOff = ((wn*48 + (lane&15))*40 + (lane>>4)*8)*2;

        float acc[2][6][4];
        #pragma unroll
        for (int f = 0; f < 2; ++f)
            #pragma unroll
            for (int g = 0; g < 6; ++g)
                #pragma unroll
                for (int i = 0; i < 4; ++i) acc[f][g][i] = 0.f;

        float av[8];
        uint4 bhv[2], blv[2];

        {
            int ih = 2*ho - 1, iw = 2*wo - 1;
            bool ok = (ih >= 0) && (iw >= 0);
            const float* ptr = xb + ((size_t)(kq*8)*H_IN + ih)*W_IN + iw;
            #pragma unroll
            for (int j = 0; j < 8; ++j)
                av[j] = ok ? __ldg(ptr + (size_t)j*H_IN*W_IN) : 0.f;
            bhv[0] = __ldg((const uint4*)(whi + brow*16 + bq4));
            blv[0] = __ldg((const uint4*)(wlo + brow*16 + bq4));
            if (tid < 256) {
                bhv[1] = __ldg((const uint4*)(whi + (128 + brow)*16 + bq4));
                blv[1] = __ldg((const uint4*)(wlo + (128 + brow)*16 + bq4));
            }
            char* stg = smem + S1_STG0;
            unsigned* sAhi = (unsigned*)(stg);
            unsigned* sAlo = (unsigned*)(stg + 10240);
            int wbase = m*20 + kq*4;
            #pragma unroll
            for (int jj = 0; jj < 4; ++jj) {
                float v0 = av[2*jj], v1 = av[2*jj+1];
                unsigned short h0 = bf16hi(v0), h1 = bf16hi(v1);
                unsigned short l0 = bf16hi(v0 - bf16f(h0));
                unsigned short l1 = bf16hi(v1 - bf16f(h1));
                sAhi[wbase + jj] = pack2(h0, h1);
                sAlo[wbase + jj] = pack2(l0, l1);
            }
            int so = (brow*20 + bq4)*4;
            *(uint4*)(stg + 20480 + so) = bhv[0];
            *(uint4*)(stg + 35840 + so) = blv[0];
            if (tid < 256) {
                int so2 = ((128 + brow)*20 + bq4)*4;
                *(uint4*)(stg + 20480 + so2) = bhv[1];
                *(uint4*)(stg + 35840 + so2) = blv[1];
            }
        }
        __syncthreads();

        for (int c = 0; c < 27; ++c) {
            const int s = c & 1;
            const unsigned stgC = S1_STG0 + s*S1_STGSZ;
            const unsigned stgN = S1_STG0 + (s^1)*S1_STGSZ;

            if (c < 26) {
                int cn = c + 1;
                int tap = cn / 3;
                int ic0 = (cn - tap*3)*32 + kq*8;
                int ki = tap / 3, kj = tap - ki*3;
                int ih = 2*ho - 1 + ki, iw = 2*wo - 1 + kj;
                bool ok = (ih >= 0) && (iw >= 0);
                const float* ptr = xb + ((size_t)ic0*H_IN + ih)*W_IN + iw;
                #pragma unroll
                for (int j = 0; j < 8; ++j)
                    av[j] = ok ? __ldg(ptr + (size_t)j*H_IN*W_IN) : 0.f;
                bhv[0] = __ldg((const uint4*)(whi + (cn*192 + brow)*16 + bq4));
                blv[0] = __ldg((const uint4*)(wlo + (cn*192 + brow)*16 + bq4));
                if (tid < 256) {
                    bhv[1] = __ldg((const uint4*)(whi + (cn*192 + 128 + brow)*16 + bq4));
                    blv[1] = __ldg((const uint4*)(wlo + (cn*192 + 128 + brow)*16 + bq4));
                }
            }

            {
                const unsigned aHiB = sb + stgC + aOff;
                const unsigned aLoB = aHiB + 10240;
                const unsigned bHiB = sb + stgC + 20480 + bOff;
                const unsigned bLoB = bHiB + 15360;
                #pragma unroll
                for (int kst = 0; kst < 2; ++kst) {
                    unsigned ko = kst*32;
                    unsigned ah[2][4], al[2][4];
                    #pragma unroll
                    for (int f = 0; f < 2; ++f) {
                        ldm4(ah[f], aHiB + f*1280 + ko);
                        ldm4(al[f], aLoB + f*1280 + ko);
                    }
                    #pragma unroll
                    for (int g2 = 0; g2 < 3; ++g2) {
                        unsigned bh[4], bl[4];
                        ldm4(bh, bHiB + g2*1280 + ko);
                        ldm4(bl, bLoB + g2*1280 + ko);
                        #pragma unroll
                        for (int f = 0; f < 2; ++f) {
                            mma_bf16(acc[f][2*g2],   ah[f], bh[0], bh[2]);
                            mma_bf16(acc[f][2*g2+1], ah[f], bh[1], bh[3]);
                            mma_bf16(acc[f][2*g2],   ah[f], bl[0], bl[2]);
                            mma_bf16(acc[f][2*g2+1], ah[f], bl[1], bl[3]);
                            mma_bf16(acc[f][2*g2],   al[f], bh[0], bh[2]);
                            mma_bf16(acc[f][2*g2+1], al[f], bh[1], bh[3]);
                        }
                    }
                }
            }

            if (c < 26) {
                char* stg = smem + stgN;
                unsigned* sAhi = (unsigned*)(stg);
                unsigned* sAlo = (unsigned*)(stg + 10240);
                int wbase = m*20 + kq*4;
                #pragma unroll
                for (int jj = 0; jj < 4; ++jj) {
                    float v0 = av[2*jj], v1 = av[2*jj+1];
                    unsigned short h0 = bf16hi(v0), h1 = bf16hi(v1);
                    unsigned short l0 = bf16hi(v0 - bf16f(h0));
                    unsigned short l1 = bf16hi(v1 - bf16f(h1));
                    sAhi[wbase + jj] = pack2(h0, h1);
                    sAlo[wbase + jj] = pack2(l0, l1);
                }
                int so = (brow*20 + bq4)*4;
                *(uint4*)(stg + 20480 + so) = bhv[0];
                *(uint4*)(stg + 35840 + so) = blv[0];
                if (tid < 256) {
                    int so2 = ((128 + brow)*20 + bq4)*4;
                    *(uint4*)(stg + 20480 + so2) = bhv[1];
                    *(uint4*)(stg + 35840 + so2) = blv[1];
                }
            }
            __syncthreads();
        }

        float* sEpi = (float*)(smem + S1_STG0);
        #pragma unroll
        for (int half = 0; half < 2; ++half) {
            if ((wm >> 1) == half) {
                #pragma unroll
                for (int f = 0; f < 2; ++f) {
                    int row0 = (wm & 1)*32 + f*16 + (lane >> 2);
                    #pragma unroll
                    for (int g = 0; g < 6; ++g) {
                        int col0 = wn*48 + g*8 + 2*(lane & 3);
                        float s0 = sbn[col0],     b0v = sbn[192 + col0];
                        float s1 = sbn[col0 + 1], b1v = sbn[192 + col0 + 1];
                        float v;
                        v = acc[f][g][0]*s0 + b0v; v = v >= 0.f ? v : 0.1f*v; sEpi[ row0   *193 + col0  ] = v;
                        v = acc[f][g][1]*s1 + b1v; v = v >= 0.f ? v : 0.1f*v; sEpi[ row0   *193 + col0+1] = v;
                        v = acc[f][g][2]*s0 + b0v; v = v >= 0.f ? v : 0.1f*v; sEpi[(row0+8)*193 + col0  ] = v;
                        v = acc[f][g][3]*s1 + b1v; v = v >= 0.f ? v : 0.1f*v; sEpi[(row0+8)*193 + col0+1] = v;
                    }
                }
            }
            __syncthreads();
            int p0 = blockIdx.x*128 + half*64;
            int bb = p0 / NPIX;
            int rb = p0 - bb*NPIX;
            #pragma unroll 4
            for (int i = 0; i < 24; ++i) {
                int idx = tid + i*512;
                int mm = idx & 63, oc = idx >> 6;
                y[((size_t)bb*192 + oc)*NPIX + rb + mm] = sEpi[mm*193 + oc];
            }
            __syncthreads();
        }
    } else {
        float* s_in = (float*)smem;
        float* s_w  = s_in + 12*1089;
        int bid = blockIdx.x - 360;
        int b  = bid / 45;
        int rr = bid - b*45;
        int ho0 = (rr / 9) * 16, wo0 = (rr - (rr/9)*9) * 16;
        const int ih0 = 2*ho0 - 1, iw0 = 2*wo0 - 1;

        const float* xb = xc_in + (size_t)b * 12 * H_IN * W_IN;
        for (int i = tid; i < 12*1089; i += 512) {
            int ic = i / 1089, j = i - ic*1089;
            int r2 = j / 33, c2 = j - r2*33;
            int ih = ih0 + r2, iw = iw0 + c2;
            s_in[i] = (ih >= 0 && ih < H_IN && iw >= 0 && iw < W_IN)
                      ? __ldg(xb + (size_t)ic*H_IN*W_IN + ih*W_IN + iw) : 0.f;
        }
        for (int i = tid; i < 2592; i += 512) s_w[i] = __ldg(wc + i);
        __syncthreads();

        if (tid < 256) {
            const int ty = tid >> 4, tx = tid & 15;
            float acc[24];
            #pragma unroll
            for (int o = 0; o < 24; ++o) acc[o] = 0.f;

            for (int ic = 0; ic < 12; ++ic) {
                float v[3][3];
                #pragma unroll
                for (int ki = 0; ki < 3; ++ki)
                    #pragma unroll
                    for (int kj = 0; kj < 3; ++kj)
                        v[ki][kj] = s_in[ic*1089 + (2*ty + ki)*33 + 2*tx + kj];
                #pragma unroll
                for (int o = 0; o < 24; ++o) {
                    float a = acc[o];
                    #pragma unroll
                    for (int ki = 0; ki < 3; ++ki)
                        #pragma unroll
                        for (int kj = 0; kj < 3; ++kj)
                            a += s_w[(o*12 + ic)*9 + ki*3 + kj] * v[ki][kj];
                    acc[o] = a;
                }
            }

            const int ho = ho0 + ty, wo = wo0 + tx;
            #pragma unroll
            for (int o = 0; o < 24; ++o) {
                float s    = __ldg(cbg + o) * rsqrtf(__ldg(cbv + o) + EPSV);
                float bias = __ldg(cbb + o) - __ldg(cbm + o) * s;
                float vv = acc[o] * s + bias;
                vv = vv >= 0.f ? vv : 0.1f * vv;
                yc[((size_t)b*24 + o)*NPIX + ho*WO + wo] = vv;
            }
        }
    }
}

// ===================== stage2: mask MMA + softmax + FUSED aggregation ========
#define M2A_HI 0
#define M2A_LO 51200
#define M2B    102400
#define M2BSZ  23040
#define SMEM_S2 (102400 + 2*23040)   // 148480

__global__ __launch_bounds__(768, 1) void stage2(
    const float* __restrict__ y1,
    const unsigned* __restrict__ whi, const unsigned* __restrict__ wlo,
    const float* __restrict__ xg, float* __restrict__ g8,
    const float* __restrict__ y1c, const float* __restrict__ w2c,
    const float* __restrict__ xc, float* __restrict__ c8)
{
    extern __shared__ char smem[];
    const int tid = threadIdx.x;

    if (blockIdx.x < 360) {
        const unsigned sb = smem_u32(smem);
        const int wid = tid >> 5, lane = tid & 31;
        const int p0 = blockIdx.x * 128;
        const int b  = p0 / NPIX;
        const int pp = p0 - b*NPIX;
        const float* yb = y1 + (size_t)b*192*NPIX + pp;

        const int brow = tid >> 2, bq4 = (tid & 3)*4;
        const bool bok = tid < 576;

        const int wm = wid & 7, wn = wid >> 3;
        const unsigned aB = sb + M2A_HI + (wm*16 + (lane&15))*400 + (lane>>4)*16;
        const unsigned bOff = ((wn*48 + (lane&15))*40 + (lane>>4)*8)*2;

        float acc[6][4];
        #pragma unroll
        for (int j = 0; j < 6; ++j)
            #pragma unroll
            for (int i = 0; i < 4; ++i) acc[j][i] = 0.f;

        {
            unsigned* sAhi = (unsigned*)(smem + M2A_HI);
            unsigned* sAlo = (unsigned*)(smem + M2A_LO);
            const int apx = tid & 127;
            const int ak0 = tid >> 7;
            #pragma unroll
            for (int j = 0; j < 16; ++j) {
                int kk = ak0 + 6*j;
                float v0 = __ldg(yb + (size_t)(2*kk)  *NPIX + apx);
                float v1 = __ldg(yb + (size_t)(2*kk+1)*NPIX + apx);
                unsigned short h0 = bf16hi(v0), h1 = bf16hi(v1);
                unsigned short l0 = bf16hi(v0 - bf16f(h0));
                unsigned short l1 = bf16hi(v1 - bf16f(h1));
                sAhi[apx*100 + kk] = pack2(h0, h1);
                sAlo[apx*100 + kk] = pack2(l0, l1);
            }
            if (bok) {
                uint4 h = __ldg((const uint4*)(whi + brow*16 + bq4));
                uint4 l = __ldg((const uint4*)(wlo + brow*16 + bq4));
                int so = (brow*20 + bq4)*4;
                *(uint4*)(smem + M2B + so) = h;
                *(uint4*)(smem + M2B + 11520 + so) = l;
            }
        }
        __syncthreads();

        uint4 bhv, blv;
        for (int c = 0; c < 6; ++c) {
            const int s = c & 1;
            if (c < 5 && bok) {
                bhv = __ldg((const uint4*)(whi + ((c+1)*144 + brow)*16 + bq4));
                blv = __ldg((const uint4*)(wlo + ((c+1)*144 + brow)*16 + bq4));
            }
            {
                const unsigned bHiB = sb + M2B + s*M2BSZ + bOff;
                const unsigned bLoB = bHiB + 11520;
                #pragma unroll
                for (int ks = 0; ks < 2; ++ks) {
                    unsigned koA = c*64 + ks*32;
                    unsigned koB = ks*32;
                    unsigned ah[4], al[4];
                    ldm4(ah, aB + koA);
                    ldm4(al, aB + (M2A_LO - M2A_HI) + koA);
                    #pragma unroll
                    for (int g2 = 0; g2 < 3; ++g2) {
                        unsigned bh[4], bl[4];
                        ldm4(bh, bHiB + g2*1280 + koB);
                        ldm4(bl, bLoB + g2*1280 + koB);
                        mma_bf16(acc[2*g2],   ah, bh[0], bh[2]);
                        mma_bf16(acc[2*g2+1], ah, bh[1], bh[3]);
                        mma_bf16(acc[2*g2],   ah, bl[0], bl[2]);
                        mma_bf16(acc[2*g2+1], ah, bl[1], bl[3]);
                        mma_bf16(acc[2*g2],   al, bh[0], bh[2]);
                        mma_bf16(acc[2*g2+1], al, bh[1], bh[3]);
                    }
                }
            }
            if (c < 5 && bok) {
                int so = (brow*20 + bq4)*4;
                *(uint4*)(smem + M2B + (s^1)*M2BSZ + so) = bhv;
                *(uint4*)(smem + M2B + (s^1)*M2BSZ + 11520 + so) = blv;
            }
            __syncthreads();
        }

        float* sC = (float*)smem;
        {
            int r0 = wm*16 + (lane >> 2);
            #pragma unroll
            for (int j = 0; j < 6; ++j) {
                int c0 = wn*48 + j*8 + 2*(lane & 3);
                sC[ r0   *145 + c0  ] = acc[j][0];
                sC[ r0   *145 + c0+1] = acc[j][1];
                sC[(r0+8)*145 + c0  ] = acc[j][2];
                sC[(r0+8)*145 + c0+1] = acc[j][3];
            }
        }
        __syncthreads();

        {
            const int sm = tid & 127;
            const int gb = tid >> 7;
            const int pp2 = pp + sm;
            const int ho = pp2 / WO, wo = pp2 - (pp2/WO)*WO;
            const float* xgb = xg + (size_t)b*96*H_IN*W_IN;
            const float* srow = sC + sm*145;

            int ihv[3], iwv[3]; bool okh[3], okw[3];
            #pragma unroll
            for (int k = 0; k < 3; ++k) {
                ihv[k] = 2*ho - 1 + k; okh[k] = (ihv[k] >= 0) && (ihv[k] < H_IN);
                iwv[k] = 2*wo - 1 + k; okw[k] = (iwv[k] >= 0) && (iwv[k] < W_IN);
            }

            #pragma unroll
            for (int i = 0; i < 3; ++i) {
                int g = gb + 6*i;
                if (g < 16) {
                    float v[9];
                    #pragma unroll
                    for (int j = 0; j < 9; ++j) v[j] = srow[g*9 + j];
                    float mx = v[0];
                    #pragma unroll
                    for (int j = 1; j < 9; ++j) mx = fmaxf(mx, v[j]);
                    float e[9], sum = 0.f;
                    #pragma unroll
                    for (int j = 0; j < 9; ++j) { e[j] = __expf(v[j] - mx); sum += e[j]; }
                    float rs = 1.f / sum;
                    float mreg[9];
                    #pragma unroll
                    for (int j = 0; j < 9; ++j) mreg[j] = e[j]*rs;

                    #pragma unroll
                    for (int cc = 0; cc < 6; ++cc) {
                        int ch = g + 16*cc;
                        const float* xcc = xgb + (size_t)ch*H_IN*W_IN;
                        float a = 0.f;
                        #pragma unroll
                        for (int ki = 0; ki < 3; ++ki)
                            #pragma unroll
                            for (int kj = 0; kj < 3; ++kj) {
                                float xv = (okh[ki] && okw[kj])
                                    ? __ldg(xcc + ihv[ki]*W_IN + iwv[kj]) : 0.f;
                                a += mreg[ki*3 + kj] * xv;
                            }
                        g8[((size_t)b*96 + ch)*NPIX + pp2] = a;
                    }
                }
            }
        }
    } else {
        float* s_w = (float*)smem;
        for (int i = tid; i < 108*24; i += 768) s_w[i] = __ldg(w2c + i);
        __syncthreads();

        int p = (blockIdx.x - 360)*768 + tid;
        int b  = p / NPIX;
        int pp = p - b*NPIX;
        const float* yb = y1c + (size_t)b*24*NPIX + pp;
        float yv[24];
        #pragma unroll
        for (int k = 0; k < 24; ++k) yv[k] = __ldg(yb + (size_t)k*NPIX);

        const int ho = pp / WO, wo = pp - (pp/WO)*WO;
        const float* xcb = xc + (size_t)b*12*H_IN*W_IN;
        int ihv[3], iwv[3]; bool okh[3], okw[3];
        #pragma unroll
        for (int k = 0; k < 3; ++k) {
            ihv[k] = 2*ho - 1 + k; okh[k] = (ihv[k] >= 0) && (ihv[k] < H_IN);
            iwv[k] = 2*wo - 1 + k; okw[k] = (iwv[k] >= 0) && (iwv[k] < W_IN);
        }

        #pragma unroll
        for (int g = 0; g < 12; ++g) {
            float lg[9];
            #pragma unroll
            for (int j = 0; j < 9; ++j) {
                const float* wr = s_w + (g*9 + j)*24;
                float a = 0.f;
                #pragma unroll
                for (int k = 0; k < 24; ++k) a += wr[k] * yv[k];
                lg[j] = a;
            }
            float mx = lg[0];
            #pragma unroll
            for (int j = 1; j < 9; ++j) mx = fmaxf(mx, lg[j]);
            float e[9], sum = 0.f;
            #pragma unroll
            for (int j = 0; j < 9; ++j) { e[j] = __expf(lg[j] - mx); sum += e[j]; }
            float rs = 1.f / sum;

            const float* xch = xcb + (size_t)g*H_IN*W_IN;
            float a = 0.f;
            #pragma unroll
            for (int ki = 0; ki < 3; ++ki)
                #pragma unroll
                for (int kj = 0; kj < 3; ++kj) {
                    float xv = (okh[ki] && okw[kj])
                        ? __ldg(xch + ihv[ki]*W_IN + iwv[kj]) : 0.f;
                    a += (e[ki*3 + kj]*rs) * xv;
                }
            c8[((size_t)b*12 + g)*NPIX + pp] = a;
        }
    }
}

// ===================== stage4: cost volumes (vectorized, 4 w per thread) =====
// gwc: block = (b2, g, h-quad). 144 thr: hh = tid/36, wq = (tid%36)*4.
// cat: block = (b2, ch, h-quad). Same thread mapping.
__global__ __launch_bounds__(144) void stage4(const float* __restrict__ g8,
                                              const float* __restrict__ c8,
                                              float* __restrict__ out)
{
    __shared__ float sbuf[4*12*WO];
    const int tid = threadIdx.x;
    const int hh = tid / 36;
    const int wq = (tid - hh*36) * 4;

    if (blockIdx.x < 2*8*(HO/4)) {
        int t = blockIdx.x;
        const int hq = t % (HO/4); t /= (HO/4);
        const int g  = t % 8;
        const int b2 = t / 8;
        const int h  = hq*4 + hh;

        const float* lp = g8 + ((size_t)(b2*96 + g*12)) * NPIX + h*WO;
        const float* rp = g8 + ((size_t)((b2+2)*96 + g*12)) * NPIX + h*WO;
        float4 lv[12];
        #pragma unroll
        for (int c = 0; c < 12; ++c) {
            lv[c] = *(const float4*)(lp + (size_t)c*NPIX + wq);
            *(float4*)(&sbuf[(hh*12 + c)*WO + wq]) = *(const float4*)(rp + (size_t)c*NPIX + wq);
        }
        __syncthreads();

        float* ob = out + ((size_t)(b2*32 + g)) * DISP * NPIX + h*WO + wq;
        const float* srow = &sbuf[hh*12*WO];
        #pragma unroll 2
        for (int d = 0; d < DISP; ++d) {
            float4 val = make_float4(0.f, 0.f, 0.f, 0.f);
            float* vp = &val.x;
            #pragma unroll
            for (int j = 0; j < 4; ++j) {
                int w = wq + j;
                if (d <= w) {
                    float s = 0.f;
                    const float* lv1 = (const float*)lv;
                    #pragma unroll
                    for (int c = 0; c < 12; ++c) s += lv1[c*4 + j] * srow[c*WO + w - d];
                    vp[j] = s * (1.f/12.f);
                }
            }
            *(float4*)(ob + (size_t)d*NPIX) = val;
        }
    } else {
        int t = blockIdx.x - 2*8*(HO/4);   // 2*24*(HO/4) blocks
        const int hq = t % (HO/4); t /= (HO/4);
        const int ch = t % 24;
        const int b2 = t / 24;
        const int h  = hq*4 + hh;

        float* ob = out + ((size_t)(b2*32 + 8 + ch)) * DISP * NPIX + h*WO + wq;
        if (ch < 12) {
            float4 vL = *(const float4*)(c8 + ((size_t)(b2*12 + ch)) * NPIX + h*WO + wq);
            const float* vp0 = &vL.x;
            #pragma unroll 4
            for (int d = 0; d < DISP; ++d) {
                float4 val;
                float* vp = &val.x;
                #pragma unroll
                for (int j = 0; j < 4; ++j)
                    vp[j] = (wq + j >= d) ? vp0[j] : 0.f;
                *(float4*)(ob + (size_t)d*NPIX) = val;
            }
        } else {
            float* srow = &sbuf[hh*WO];
            *(float4*)(&srow[wq]) =
                *(const float4*)(c8 + ((size_t)((b2+2)*12 + (ch-12))) * NPIX + h*WO + wq);
            __syncthreads();
            #pragma unroll 4
            for (int d = 0; d < DISP; ++d) {
                float4 val = make_float4(0.f, 0.f, 0.f, 0.f);
                float* vp = &val.x;
                #pragma unroll
                for (int j = 0; j < 4; ++j) {
                    int w = wq + j;
                    if (w >= d) vp[j] = srow[w - d];
                }
                *(float4*)(ob + (size_t)d*NPIX) = val;
            }
        }
    }
}

// ------------------- launch --------------------------------------------------
extern "C" void kernel_launch(void* const* d_in, const int* in_sizes, int n_in,
                              void* d_out, int out_size)
{
    const float* gwc_f = (const float*)d_in[0];
    const float* cat_f = (const float*)d_in[1];
    const float* g_w1  = (const float*)d_in[2];
    const float* g_bg  = (const float*)d_in[3];
    const float* g_bb  = (const float*)d_in[4];
    const float* g_bm  = (const float*)d_in[5];
    const float* g_bv  = (const float*)d_in[6];
    const float* g_w2  = (const float*)d_in[7];
    const float* c_w1  = (const float*)d_in[8];
    const float* c_bg  = (const float*)d_in[9];
    const float* c_bb  = (const float*)d_in[10];
    const float* c_bm  = (const float*)d_in[11];
    const float* c_bv  = (const float*)d_in[12];
    const float* c_w2  = (const float*)d_in[13];
    float* out = (float*)d_out;

    float *y1g, *y1c, *g8, *c8;
    unsigned *wc1hi, *wc1lo, *w2hi, *w2lo;
    cudaGetSymbolAddress((void**)&y1g, g_y1g);
    cudaGetSymbolAddress((void**)&y1c, g_y1c);
    cudaGetSymbolAddress((void**)&g8,  g_g8);
    cudaGetSymbolAddress((void**)&c8,  g_c8);
    cudaGetSymbolAddress((void**)&wc1hi, g_wc1hi);
    cudaGetSymbolAddress((void**)&wc1lo, g_wc1lo);
    cudaGetSymbolAddress((void**)&w2hi,  g_w2hi);
    cudaGetSymbolAddress((void**)&w2lo,  g_w2lo);

    // 0) weight prep
    wprep<<<(27*192*16 + 6*144*16 + 255)/256, 256>>>(g_w1, g_w2, wc1hi, wc1lo, w2hi, w2lo);

    // 1) conv1 gwc (MMA) + conv1 cat
    cudaFuncSetAttribute(stage1, cudaFuncAttributeMaxDynamicSharedMemorySize, SMEM_S1);
    stage1<<<360 + BATCH*45, 512, SMEM_S1>>>(gwc_f, wc1hi, wc1lo, g_bg, g_bb, g_bm, g_bv, y1g,
                                             cat_f, c_w1, c_bg, c_bb, c_bm, c_bv, y1c);

    // 2) mask MMA + softmax + fused aggregation (gwc + cat)
    cudaFuncSetAttribute(stage2, cudaFuncAttributeMaxDynamicSharedMemorySize, SMEM_S2);
    stage2<<<360 + 60, 768, SMEM_S2>>>(y1g, w2hi, w2lo, gwc_f, g8, y1c, c_w2, cat_f, c8);

    // 3) cost volumes (vectorized)
    stage4<<<2*8*(HO/4) + 2*24*(HO/4), 144>>>(g8, c8, out);
}

// round 17
// speedup vs baseline: 1.0932x; 1.0932x over previous
#include <cuda_runtime.h>
#include <cstdint>

#define H_IN 160
#define W_IN 288
#define HO   80
#define WO   144
#define NPIX (HO*WO)          // 11520
#define BATCH 4
#define EPSV 1e-5f
#define DISP 24

// ------------------- scratch (static device memory, no allocs) ---------------
__device__ float g_y1g[BATCH*192*NPIX];
__device__ float g_y1c[BATCH*24*NPIX];
__device__ float g_g8 [BATCH*96*NPIX];
__device__ float g_c8 [BATCH*12*NPIX];
__device__ unsigned g_wc1hi[27*192*16];
__device__ unsigned g_wc1lo[27*192*16];
__device__ unsigned g_w2hi [6*144*16];
__device__ unsigned g_w2lo [6*144*16];

// ===================== small helpers ========================================
__device__ __forceinline__ unsigned smem_u32(const void* p){
    unsigned a;
    asm("{ .reg .u64 t; cvta.to.shared.u64 t, %1; cvt.u32.u64 %0, t; }"
        : "=r"(a) : "l"(p));
    return a;
}
__device__ __forceinline__ unsigned short bf16hi(float x){
    unsigned u = __float_as_uint(x);
    unsigned r = u + 0x7fffu + ((u >> 16) & 1u);
    return (unsigned short)(r >> 16);
}
__device__ __forceinline__ float bf16f(unsigned short h){
    return __uint_as_float(((unsigned)h) << 16);
}
__device__ __forceinline__ unsigned pack2(unsigned short a, unsigned short b){
    return (unsigned)a | ((unsigned)b << 16);
}
__device__ __forceinline__ void ldm4(unsigned* r, unsigned addr){
    asm volatile("ldmatrix.sync.aligned.m8n8.x4.shared.b16 {%0,%1,%2,%3}, [%4];"
        : "=r"(r[0]), "=r"(r[1]), "=r"(r[2]), "=r"(r[3]) : "r"(addr));
}
__device__ __forceinline__ void mma_bf16(float* c, const unsigned* a,
                                         unsigned b0, unsigned b1){
    asm volatile("mma.sync.aligned.m16n8k16.row.col.f32.bf16.bf16.f32 "
        "{%0,%1,%2,%3}, {%4,%5,%6,%7}, {%8,%9}, {%0,%1,%2,%3};"
        : "+f"(c[0]), "+f"(c[1]), "+f"(c[2]), "+f"(c[3])
        : "r"(a[0]), "r"(a[1]), "r"(a[2]), "r"(a[3]), "r"(b0), "r"(b1));
}

// ===================== weight prep ==========================================
__global__ __launch_bounds__(256) void wprep(const float* __restrict__ w1,
                                             const float* __restrict__ w2,
                                             unsigned* __restrict__ w1hi,
                                             unsigned* __restrict__ w1lo,
                                             unsigned* __restrict__ w2hi,
                                             unsigned* __restrict__ w2lo)
{
    int idx = blockIdx.x * 256 + threadIdx.x;
    if (idx < 27*192*16) {
        int kk = idx & 15;
        int row = (idx >> 4) % 192;
        int c   = idx / (192*16);
        int k0 = c*32 + 2*kk, k1 = k0 + 1;
        int tap0 = k0 / 96, ic0 = k0 - tap0*96;
        int tap1 = k1 / 96, ic1 = k1 - tap1*96;
        float v0 = w1[row*864 + ic0*9 + tap0];
        float v1 = w1[row*864 + ic1*9 + tap1];
        unsigned short h0 = bf16hi(v0), h1 = bf16hi(v1);
        w1hi[idx] = pack2(h0, h1);
        w1lo[idx] = pack2(bf16hi(v0 - bf16f(h0)), bf16hi(v1 - bf16f(h1)));
    } else {
        int j = idx - 27*192*16;
        if (j >= 6*144*16) return;
        int kk = j & 15;
        int row = (j >> 4) % 144;
        int c   = j / (144*16);
        int k0 = c*32 + 2*kk;
        float v0 = w2[row*192 + k0];
        float v1 = w2[row*192 + k0 + 1];
        unsigned short h0 = bf16hi(v0), h1 = bf16hi(v1);
        w2hi[j] = pack2(h0, h1);
        w2lo[j] = pack2(bf16hi(v0 - bf16f(h0)), bf16hi(v1 - bf16f(h1)));
    }
}

// ===================== stage1: conv1 gwc(MMA,512thr, double-buffered) + cat ==
#define S1_STG0 1536
#define S1_STGSZ 51200
#define SMEM_S1 (1536 + 2*S1_STGSZ)   // 103936

__global__ __launch_bounds__(512, 1) void stage1(
    const float* __restrict__ x,
    const unsigned* __restrict__ whi, const unsigned* __restrict__ wlo,
    const float* __restrict__ bng, const float* __restrict__ bnb,
    const float* __restrict__ bnm, const float* __restrict__ bnv,
    float* __restrict__ y,
    const float* __restrict__ xc_in, const float* __restrict__ wc,
    const float* __restrict__ cbg, const float* __restrict__ cbb,
    const float* __restrict__ cbm, const float* __restrict__ cbv,
    float* __restrict__ yc)
{
    extern __shared__ char smem[];
    const int tid = threadIdx.x;

    if (blockIdx.x < 360) {
        const unsigned sb = smem_u32(smem);
        const int wid = tid >> 5, lane = tid & 31;
        float* sbn = (float*)smem;

        if (tid < 192) {
            float s = bng[tid] * rsqrtf(bnv[tid] + EPSV);
            sbn[tid] = s;
            sbn[192 + tid] = bnb[tid] - bnm[tid] * s;
        }

        const int m  = tid & 127;
        const int kq = tid >> 7;
        const int p  = blockIdx.x*128 + m;
        const int b  = p / NPIX;
        const int r  = p - b*NPIX;
        const int ho = r / WO, wo = r - (r/WO)*WO;
        const float* xb = x + (size_t)b * 96 * H_IN * W_IN;

        const int brow = tid >> 2, bq4 = (tid & 3)*4;

        const int wm = wid & 3, wn = wid >> 2;
        const unsigned aOff = ((wm*32 + (lane&15))*40 + (lane>>4)*8)*2;
        const unsigned bOff = ((wn*48 + (lane&15))*40 + (lane>>4)*8)*2;

        float acc[2][6][4];
        #pragma unroll
        for (int f = 0; f < 2; ++f)
            #pragma unroll
            for (int g = 0; g < 6; ++g)
                #pragma unroll
                for (int i = 0; i < 4; ++i) acc[f][g][i] = 0.f;

        float av[8];
        uint4 bhv[2], blv[2];

        {
            int ih = 2*ho - 1, iw = 2*wo - 1;
            bool ok = (ih >= 0) && (iw >= 0);
            const float* ptr = xb + ((size_t)(kq*8)*H_IN + ih)*W_IN + iw;
            #pragma unroll
            for (int j = 0; j < 8; ++j)
                av[j] = ok ? __ldg(ptr + (size_t)j*H_IN*W_IN) : 0.f;
            bhv[0] = __ldg((const uint4*)(whi + brow*16 + bq4));
            blv[0] = __ldg((const uint4*)(wlo + brow*16 + bq4));
            if (tid < 256) {
                bhv[1] = __ldg((const uint4*)(whi + (128 + brow)*16 + bq4));
                blv[1] = __ldg((const uint4*)(wlo + (128 + brow)*16 + bq4));
            }
            char* stg = smem + S1_STG0;
            unsigned* sAhi = (unsigned*)(stg);
            unsigned* sAlo = (unsigned*)(stg + 10240);
            int wbase = m*20 + kq*4;
            #pragma unroll
            for (int jj = 0; jj < 4; ++jj) {
                float v0 = av[2*jj], v1 = av[2*jj+1];
                unsigned short h0 = bf16hi(v0), h1 = bf16hi(v1);
                unsigned short l0 = bf16hi(v0 - bf16f(h0));
                unsigned short l1 = bf16hi(v1 - bf16f(h1));
                sAhi[wbase + jj] = pack2(h0, h1);
                sAlo[wbase + jj] = pack2(l0, l1);
            }
            int so = (brow*20 + bq4)*4;
            *(uint4*)(stg + 20480 + so) = bhv[0];
            *(uint4*)(stg + 35840 + so) = blv[0];
            if (tid < 256) {
                int so2 = ((128 + brow)*20 + bq4)*4;
                *(uint4*)(stg + 20480 + so2) = bhv[1];
                *(uint4*)(stg + 35840 + so2) = blv[1];
            }
        }
        __syncthreads();

        for (int c = 0; c < 27; ++c) {
            const int s = c & 1;
            const unsigned stgC = S1_STG0 + s*S1_STGSZ;
            const unsigned stgN = S1_STG0 + (s^1)*S1_STGSZ;

            if (c < 26) {
                int cn = c + 1;
                int tap = cn / 3;
                int ic0 = (cn - tap*3)*32 + kq*8;
                int ki = tap / 3, kj = tap - ki*3;
                int ih = 2*ho - 1 + ki, iw = 2*wo - 1 + kj;
                bool ok = (ih >= 0) && (iw >= 0);
                const float* ptr = xb + ((size_t)ic0*H_IN + ih)*W_IN + iw;
                #pragma unroll
                for (int j = 0; j < 8; ++j)
                    av[j] = ok ? __ldg(ptr + (size_t)j*H_IN*W_IN) : 0.f;
                bhv[0] = __ldg((const uint4*)(whi + (cn*192 + brow)*16 + bq4));
                blv[0] = __ldg((const uint4*)(wlo + (cn*192 + brow)*16 + bq4));
                if (tid < 256) {
                    bhv[1] = __ldg((const uint4*)(whi + (cn*192 + 128 + brow)*16 + bq4));
                    blv[1] = __ldg((const uint4*)(wlo + (cn*192 + 128 + brow)*16 + bq4));
                }
            }

            {
                const unsigned aHiB = sb + stgC + aOff;
                const unsigned aLoB = aHiB + 10240;
                const unsigned bHiB = sb + stgC + 20480 + bOff;
                const unsigned bLoB = bHiB + 15360;
                #pragma unroll
                for (int kst = 0; kst < 2; ++kst) {
                    unsigned ko = kst*32;
                    unsigned ah[2][4], al[2][4];
                    #pragma unroll
                    for (int f = 0; f < 2; ++f) {
                        ldm4(ah[f], aHiB + f*1280 + ko);
                        ldm4(al[f], aLoB + f*1280 + ko);
                    }
                    #pragma unroll
                    for (int g2 = 0; g2 < 3; ++g2) {
                        unsigned bh[4], bl[4];
                        ldm4(bh, bHiB + g2*1280 + ko);
                        ldm4(bl, bLoB + g2*1280 + ko);
                        #pragma unroll
                        for (int f = 0; f < 2; ++f) {
                            mma_bf16(acc[f][2*g2],   ah[f], bh[0], bh[2]);
                            mma_bf16(acc[f][2*g2+1], ah[f], bh[1], bh[3]);
                            mma_bf16(acc[f][2*g2],   ah[f], bl[0], bl[2]);
                            mma_bf16(acc[f][2*g2+1], ah[f], bl[1], bl[3]);
                            mma_bf16(acc[f][2*g2],   al[f], bh[0], bh[2]);
                            mma_bf16(acc[f][2*g2+1], al[f], bh[1], bh[3]);
                        }
                    }
                }
            }

            if (c < 26) {
                char* stg = smem + stgN;
                unsigned* sAhi = (unsigned*)(stg);
                unsigned* sAlo = (unsigned*)(stg + 10240);
                int wbase = m*20 + kq*4;
                #pragma unroll
                for (int jj = 0; jj < 4; ++jj) {
                    float v0 = av[2*jj], v1 = av[2*jj+1];
                    unsigned short h0 = bf16hi(v0), h1 = bf16hi(v1);
                    unsigned short l0 = bf16hi(v0 - bf16f(h0));
                    unsigned short l1 = bf16hi(v1 - bf16f(h1));
                    sAhi[wbase + jj] = pack2(h0, h1);
                    sAlo[wbase + jj] = pack2(l0, l1);
                }
                int so = (brow*20 + bq4)*4;
                *(uint4*)(stg + 20480 + so) = bhv[0];
                *(uint4*)(stg + 35840 + so) = blv[0];
                if (tid < 256) {
                    int so2 = ((128 + brow)*20 + bq4)*4;
                    *(uint4*)(stg + 20480 + so2) = bhv[1];
                    *(uint4*)(stg + 35840 + so2) = blv[1];
                }
            }
            __syncthreads();
        }

        float* sEpi = (float*)(smem + S1_STG0);
        #pragma unroll
        for (int half = 0; half < 2; ++half) {
            if ((wm >> 1) == half) {
                #pragma unroll
                for (int f = 0; f < 2; ++f) {
                    int row0 = (wm & 1)*32 + f*16 + (lane >> 2);
                    #pragma unroll
                    for (int g = 0; g < 6; ++g) {
                        int col0 = wn*48 + g*8 + 2*(lane & 3);
                        float s0 = sbn[col0],     b0v = sbn[192 + col0];
                        float s1 = sbn[col0 + 1], b1v = sbn[192 + col0 + 1];
                        float v;
                        v = acc[f][g][0]*s0 + b0v; v = v >= 0.f ? v : 0.1f*v; sEpi[ row0   *193 + col0  ] = v;
                        v = acc[f][g][1]*s1 + b1v; v = v >= 0.f ? v : 0.1f*v; sEpi[ row0   *193 + col0+1] = v;
                        v = acc[f][g][2]*s0 + b0v; v = v >= 0.f ? v : 0.1f*v; sEpi[(row0+8)*193 + col0  ] = v;
                        v = acc[f][g][3]*s1 + b1v; v = v >= 0.f ? v : 0.1f*v; sEpi[(row0+8)*193 + col0+1] = v;
                    }
                }
            }
            __syncthreads();
            int p0 = blockIdx.x*128 + half*64;
            int bb = p0 / NPIX;
            int rb = p0 - bb*NPIX;
            #pragma unroll 4
            for (int i = 0; i < 24; ++i) {
                int idx = tid + i*512;
                int mm = idx & 63, oc = idx >> 6;
                y[((size_t)bb*192 + oc)*NPIX + rb + mm] = sEpi[mm*193 + oc];
            }
            __syncthreads();
        }
    } else {
        float* s_in = (float*)smem;
        float* s_w  = s_in + 12*1089;
        int bid = blockIdx.x - 360;
        int b  = bid / 45;
        int rr = bid - b*45;
        int ho0 = (rr / 9) * 16, wo0 = (rr - (rr/9)*9) * 16;
        const int ih0 = 2*ho0 - 1, iw0 = 2*wo0 - 1;

        const float* xb = xc_in + (size_t)b * 12 * H_IN * W_IN;
        for (int i = tid; i < 12*1089; i += 512) {
            int ic = i / 1089, j = i - ic*1089;
            int r2 = j / 33, c2 = j - r2*33;
            int ih = ih0 + r2, iw = iw0 + c2;
            s_in[i] = (ih >= 0 && ih < H_IN && iw >= 0 && iw < W_IN)
                      ? __ldg(xb + (size_t)ic*H_IN*W_IN + ih*W_IN + iw) : 0.f;
        }
        for (int i = tid; i < 2592; i += 512) s_w[i] = __ldg(wc + i);
        __syncthreads();

        if (tid < 256) {
            const int ty = tid >> 4, tx = tid & 15;
            float acc[24];
            #pragma unroll
            for (int o = 0; o < 24; ++o) acc[o] = 0.f;

            for (int ic = 0; ic < 12; ++ic) {
                float v[3][3];
                #pragma unroll
                for (int ki = 0; ki < 3; ++ki)
                    #pragma unroll
                    for (int kj = 0; kj < 3; ++kj)
                        v[ki][kj] = s_in[ic*1089 + (2*ty + ki)*33 + 2*tx + kj];
                #pragma unroll
                for (int o = 0; o < 24; ++o) {
                    float a = acc[o];
                    #pragma unroll
                    for (int ki = 0; ki < 3; ++ki)
                        #pragma unroll
                        for (int kj = 0; kj < 3; ++kj)
                            a += s_w[(o*12 + ic)*9 + ki*3 + kj] * v[ki][kj];
                    acc[o] = a;
                }
            }

            const int ho = ho0 + ty, wo = wo0 + tx;
            #pragma unroll
            for (int o = 0; o < 24; ++o) {
                float s    = __ldg(cbg + o) * rsqrtf(__ldg(cbv + o) + EPSV);
                float bias = __ldg(cbb + o) - __ldg(cbm + o) * s;
                float vv = acc[o] * s + bias;
                vv = vv >= 0.f ? vv : 0.1f * vv;
                yc[((size_t)b*24 + o)*NPIX + ho*WO + wo] = vv;
            }
        }
    }
}

// ===================== stage2: mask MMA + softmax + FUSED aggregation ========
#define M2A_HI 0
#define M2A_LO 51200
#define M2B    102400
#define M2BSZ  23040
#define SMEM_S2 (102400 + 2*23040)   // 148480

__global__ __launch_bounds__(768, 1) void stage2(
    const float* __restrict__ y1,
    const unsigned* __restrict__ whi, const unsigned* __restrict__ wlo,
    const float* __restrict__ xg, float* __restrict__ g8,
    const float* __restrict__ y1c, const float* __restrict__ w2c,
    const float* __restrict__ xc, float* __restrict__ c8)
{
    extern __shared__ char smem[];
    const int tid = threadIdx.x;

    if (blockIdx.x < 360) {
        const unsigned sb = smem_u32(smem);
        const int wid = tid >> 5, lane = tid & 31;
        const int p0 = blockIdx.x * 128;
        const int b  = p0 / NPIX;
        const int pp = p0 - b*NPIX;
        const float* yb = y1 + (size_t)b*192*NPIX + pp;

        const int brow = tid >> 2, bq4 = (tid & 3)*4;
        const bool bok = tid < 576;

        const int wm = wid & 7, wn = wid >> 3;
        const unsigned aB = sb + M2A_HI + (wm*16 + (lane&15))*400 + (lane>>4)*16;
        const unsigned bOff = ((wn*48 + (lane&15))*40 + (lane>>4)*8)*2;

        float acc[6][4];
        #pragma unroll
        for (int j = 0; j < 6; ++j)
            #pragma unroll
            for (int i = 0; i < 4; ++i) acc[j][i] = 0.f;

        {
            unsigned* sAhi = (unsigned*)(smem + M2A_HI);
            unsigned* sAlo = (unsigned*)(smem + M2A_LO);
            const int apx = tid & 127;
            const int ak0 = tid >> 7;
            #pragma unroll
            for (int j = 0; j < 16; ++j) {
                int kk = ak0 + 6*j;
                float v0 = __ldg(yb + (size_t)(2*kk)  *NPIX + apx);
                float v1 = __ldg(yb + (size_t)(2*kk+1)*NPIX + apx);
                unsigned short h0 = bf16hi(v0), h1 = bf16hi(v1);
                unsigned short l0 = bf16hi(v0 - bf16f(h0));
                unsigned short l1 = bf16hi(v1 - bf16f(h1));
                sAhi[apx*100 + kk] = pack2(h0, h1);
                sAlo[apx*100 + kk] = pack2(l0, l1);
            }
            if (bok) {
                uint4 h = __ldg((const uint4*)(whi + brow*16 + bq4));
                uint4 l = __ldg((const uint4*)(wlo + brow*16 + bq4));
                int so = (brow*20 + bq4)*4;
                *(uint4*)(smem + M2B + so) = h;
                *(uint4*)(smem + M2B + 11520 + so) = l;
            }
        }
        __syncthreads();

        uint4 bhv, blv;
        for (int c = 0; c < 6; ++c) {
            const int s = c & 1;
            if (c < 5 && bok) {
                bhv = __ldg((const uint4*)(whi + ((c+1)*144 + brow)*16 + bq4));
                blv = __ldg((const uint4*)(wlo + ((c+1)*144 + brow)*16 + bq4));
            }
            {
                const unsigned bHiB = sb + M2B + s*M2BSZ + bOff;
                const unsigned bLoB = bHiB + 11520;
                #pragma unroll
                for (int ks = 0; ks < 2; ++ks) {
                    unsigned koA = c*64 + ks*32;
                    unsigned koB = ks*32;
                    unsigned ah[4], al[4];
                    ldm4(ah, aB + koA);
                    ldm4(al, aB + (M2A_LO - M2A_HI) + koA);
                    #pragma unroll
                    for (int g2 = 0; g2 < 3; ++g2) {
                        unsigned bh[4], bl[4];
                        ldm4(bh, bHiB + g2*1280 + koB);
                        ldm4(bl, bLoB + g2*1280 + koB);
                        mma_bf16(acc[2*g2],   ah, bh[0], bh[2]);
                        mma_bf16(acc[2*g2+1], ah, bh[1], bh[3]);
                        mma_bf16(acc[2*g2],   ah, bl[0], bl[2]);
                        mma_bf16(acc[2*g2+1], ah, bl[1], bl[3]);
                        mma_bf16(acc[2*g2],   al, bh[0], bh[2]);
                        mma_bf16(acc[2*g2+1], al, bh[1], bh[3]);
                    }
                }
            }
            if (c < 5 && bok) {
                int so = (brow*20 + bq4)*4;
                *(uint4*)(smem + M2B + (s^1)*M2BSZ + so) = bhv;
                *(uint4*)(smem + M2B + (s^1)*M2BSZ + 11520 + so) = blv;
            }
            __syncthreads();
        }

        float* sC = (float*)smem;
        {
            int r0 = wm*16 + (lane >> 2);
            #pragma unroll
            for (int j = 0; j < 6; ++j) {
                int c0 = wn*48 + j*8 + 2*(lane & 3);
                sC[ r0   *145 + c0  ] = acc[j][0];
                sC[ r0   *145 + c0+1] = acc[j][1];
                sC[(r0+8)*145 + c0  ] = acc[j][2];
                sC[(r0+8)*145 + c0+1] = acc[j][3];
            }
        }
        __syncthreads();

        {
            const int sm = tid & 127;
            const int gb = tid >> 7;
            const int pp2 = pp + sm;
            const int ho = pp2 / WO, wo = pp2 - (pp2/WO)*WO;
            const float* xgb = xg + (size_t)b*96*H_IN*W_IN;
            const float* srow = sC + sm*145;

            int ihv[3], iwv[3]; bool okh[3], okw[3];
            #pragma unroll
            for (int k = 0; k < 3; ++k) {
                ihv[k] = 2*ho - 1 + k; okh[k] = (ihv[k] >= 0) && (ihv[k] < H_IN);
                iwv[k] = 2*wo - 1 + k; okw[k] = (iwv[k] >= 0) && (iwv[k] < W_IN);
            }

            #pragma unroll
            for (int i = 0; i < 3; ++i) {
                int g = gb + 6*i;
                if (g < 16) {
                    float v[9];
                    #pragma unroll
                    for (int j = 0; j < 9; ++j) v[j] = srow[g*9 + j];
                    float mx = v[0];
                    #pragma unroll
                    for (int j = 1; j < 9; ++j) mx = fmaxf(mx, v[j]);
                    float e[9], sum = 0.f;
                    #pragma unroll
                    for (int j = 0; j < 9; ++j) { e[j] = __expf(v[j] - mx); sum += e[j]; }
                    float rs = 1.f / sum;
                    float mreg[9];
                    #pragma unroll
                    for (int j = 0; j < 9; ++j) mreg[j] = e[j]*rs;

                    #pragma unroll
                    for (int cc = 0; cc < 6; ++cc) {
                        int ch = g + 16*cc;
                        const float* xcc = xgb + (size_t)ch*H_IN*W_IN;
                        float a = 0.f;
                        #pragma unroll
                        for (int ki = 0; ki < 3; ++ki)
                            #pragma unroll
                            for (int kj = 0; kj < 3; ++kj) {
                                float xv = (okh[ki] && okw[kj])
                                    ? __ldg(xcc + ihv[ki]*W_IN + iwv[kj]) : 0.f;
                                a += mreg[ki*3 + kj] * xv;
                            }
                        g8[((size_t)b*96 + ch)*NPIX + pp2] = a;
                    }
                }
            }
        }
    } else {
        float* s_w = (float*)smem;
        for (int i = tid; i < 108*24; i += 768) s_w[i] = __ldg(w2c + i);
        __syncthreads();

        int p = (blockIdx.x - 360)*768 + tid;
        int b  = p / NPIX;
        int pp = p - b*NPIX;
        const float* yb = y1c + (size_t)b*24*NPIX + pp;
        float yv[24];
        #pragma unroll
        for (int k = 0; k < 24; ++k) yv[k] = __ldg(yb + (size_t)k*NPIX);

        const int ho = pp / WO, wo = pp - (pp/WO)*WO;
        const float* xcb = xc + (size_t)b*12*H_IN*W_IN;
        int ihv[3], iwv[3]; bool okh[3], okw[3];
        #pragma unroll
        for (int k = 0; k < 3; ++k) {
            ihv[k] = 2*ho - 1 + k; okh[k] = (ihv[k] >= 0) && (ihv[k] < H_IN);
            iwv[k] = 2*wo - 1 + k; okw[k] = (iwv[k] >= 0) && (iwv[k] < W_IN);
        }

        #pragma unroll
        for (int g = 0; g < 12; ++g) {
            float lg[9];
            #pragma unroll
            for (int j = 0; j < 9; ++j) {
                const float* wr = s_w + (g*9 + j)*24;
                float a = 0.f;
                #pragma unroll
                for (int k = 0; k < 24; ++k) a += wr[k] * yv[k];
                lg[j] = a;
            }
            float mx = lg[0];
            #pragma unroll
            for (int j = 1; j < 9; ++j) mx = fmaxf(mx, lg[j]);
            float e[9], sum = 0.f;
            #pragma unroll
            for (int j = 0; j < 9; ++j) { e[j] = __expf(lg[j] - mx); sum += e[j]; }
            float rs = 1.f / sum;

            const float* xch = xcb + (size_t)g*H_IN*W_IN;
            float a = 0.f;
            #pragma unroll
            for (int ki = 0; ki < 3; ++ki)
                #pragma unroll
                for (int kj = 0; kj < 3; ++kj) {
                    float xv = (okh[ki] && okw[kj])
                        ? __ldg(xch + ihv[ki]*W_IN + iwv[kj]) : 0.f;
                    a += (e[ki*3 + kj]*rs) * xv;
                }
            c8[((size_t)b*12 + g)*NPIX + pp] = a;
        }
    }
}

// ===================== stage4: cost volumes ==================================
__global__ __launch_bounds__(144) void stage4(const float* __restrict__ g8,
                                              const float* __restrict__ c8,
                                              float* __restrict__ out)
{
    __shared__ float sbuf[12*WO];
    const int w = threadIdx.x;

    if (blockIdx.x < 2*8*HO) {
        int t = blockIdx.x;
        const int h  = t % HO; t /= HO;
        const int g  = t % 8;
        const int b2 = t / 8;

        const float* lp = g8 + ((size_t)(b2*96 + g*12)) * NPIX + h*WO;
        const float* rp = g8 + ((size_t)((b2+2)*96 + g*12)) * NPIX + h*WO;
        float lv[12];
        #pragma unroll
        for (int c = 0; c < 12; ++c) {
            lv[c] = lp[(size_t)c*NPIX + w];
            sbuf[c*WO + w] = rp[(size_t)c*NPIX + w];
        }
        __syncthreads();

        float* ob = out + ((size_t)(b2*32 + g)) * DISP * NPIX + h*WO + w;
        #pragma unroll 4
        for (int d = 0; d < DISP; ++d) {
            float val = 0.f;
            if (d <= w) {
                float s = 0.f;
                #pragma unroll
                for (int c = 0; c < 12; ++c) s += lv[c] * sbuf[c*WO + w - d];
                val = s * (1.f/12.f);
            }
            ob[(size_t)d*NPIX] = val;
        }
    } else {
        int t = blockIdx.x - 2*8*HO;
        const int h  = t % HO; t /= HO;
        const int ch = t % 24;
        const int b2 = t / 24;

        float* ob = out + ((size_t)(b2*32 + 8 + ch)) * DISP * NPIX + h*WO + w;
        if (ch < 12) {
            float vL = __ldg(c8 + ((size_t)(b2*12 + ch)) * NPIX + h*WO + w);
            #pragma unroll 4
            for (int d = 0; d < DISP; ++d)
                ob[(size_t)d*NPIX] = (w >= d) ? vL : 0.f;
        } else {
            sbuf[w] = __ldg(c8 + ((size_t)((b2+2)*12 + (ch-12))) * NPIX + h*WO + w);
            __syncthreads();
            #pragma unroll 4
            for (int d = 0; d < DISP; ++d)
                ob[(size_t)d*NPIX] = (w >= d) ? sbuf[w - d] : 0.f;
        }
    }
}

// ------------------- launch --------------------------------------------------
extern "C" void kernel_launch(void* const* d_in, const int* in_sizes, int n_in,
                              void* d_out, int out_size)
{
    const float* gwc_f = (const float*)d_in[0];
    const float* cat_f = (const float*)d_in[1];
    const float* g_w1  = (const float*)d_in[2];
    const float* g_bg  = (const float*)d_in[3];
    const float* g_bb  = (const float*)d_in[4];
    const float* g_bm  = (const float*)d_in[5];
    const float* g_bv  = (const float*)d_in[6];
    const float* g_w2  = (const float*)d_in[7];
    const float* c_w1  = (const float*)d_in[8];
    const float* c_bg  = (const float*)d_in[9];
    const float* c_bb  = (const float*)d_in[10];
    const float* c_bm  = (const float*)d_in[11];
    const float* c_bv  = (const float*)d_in[12];
    const float* c_w2  = (const float*)d_in[13];
    float* out = (float*)d_out;

    float *y1g, *y1c, *g8, *c8;
    unsigned *wc1hi, *wc1lo, *w2hi, *w2lo;
    cudaGetSymbolAddress((void**)&y1g, g_y1g);
    cudaGetSymbolAddress((void**)&y1c, g_y1c);
    cudaGetSymbolAddress((void**)&g8,  g_g8);
    cudaGetSymbolAddress((void**)&c8,  g_c8);
    cudaGetSymbolAddress((void**)&wc1hi, g_wc1hi);
    cudaGetSymbolAddress((void**)&wc1lo, g_wc1lo);
    cudaGetSymbolAddress((void**)&w2hi,  g_w2hi);
    cudaGetSymbolAddress((void**)&w2lo,  g_w2lo);

    // 0) weight prep
    wprep<<<(27*192*16 + 6*144*16 + 255)/256, 256>>>(g_w1, g_w2, wc1hi, wc1lo, w2hi, w2lo);

    // 1) conv1 gwc (MMA) + conv1 cat
    cudaFuncSetAttribute(stage1, cudaFuncAttributeMaxDynamicSharedMemorySize, SMEM_S1);
    stage1<<<360 + BATCH*45, 512, SMEM_S1>>>(gwc_f, wc1hi, wc1lo, g_bg, g_bb, g_bm, g_bv, y1g,
                                             cat_f, c_w1, c_bg, c_bb, c_bm, c_bv, y1c);

    // 2) mask MMA + softmax + fused aggregation (gwc + cat)
    cudaFuncSetAttribute(stage2, cudaFuncAttributeMaxDynamicSharedMemorySize, SMEM_S2);
    stage2<<<360 + 60, 768, SMEM_S2>>>(y1g, w2hi, w2lo, gwc_f, g8, y1c, c_w2, cat_f, c8);

    // 3) cost volumes
    stage4<<<2*8*HO + 2*24*HO, 144>>>(g8, c8, out);
}